// round 11
// baseline (speedup 1.0000x reference)
#include <cuda_runtime.h>

#define NR 1024
#define NC 1024
#define NN (NR*NC)

#define TS   24              // output tile side
#define H    6               // halo (6 one-ring stages)
#define REG  36              // TS + 2*H
#define REG2 (REG*REG)
#define NQR  9               // 1x4 quads per region row (lc = 0,4,...,32)
#define NROWS 34             // region rows [1,35)
#define NQUAD (NQR*NROWS)    // 306
#define NTHR 320
#define NTILE ((NR + TS - 1) / TS)   // 43
#define SBUF (REG2 + 2*REG)  // one guard row each side

// persistent scratch
__device__ float g_W[8 * NN];   // planar per-offset weights [o][i]
__device__ float g_yA[NN];
__device__ float g_yB[NN];

// Tsit5 coefficients
#define DT (1.0f/32.0f)
#define A21  0.161f
#define A31 -0.008480655492356989f
#define A32  0.335480655492357f
#define A41  2.8971530571054935f
#define A42 -6.359448489975075f
#define A43  4.3622954328695815f
#define A51  5.325864828439257f
#define A52 -11.748883564062828f
#define A53  7.4955393428898365f
#define A54 -0.09249506636175525f
#define A61  5.86145544294642f
#define A62 -12.92096931784711f
#define A63  8.159367898576159f
#define A64 -0.071584973281401f
#define A65 -0.028269050394068383f
#define B1   0.09646076681806523f
#define B2   0.01f
#define B3   0.4798896504144996f
#define B4   1.379008574103742f
#define B5  -3.290069515436081f
#define B6   2.324710524099774f

__device__ __forceinline__ float act(float v) {
    // fmaxf/fminf drop NaN operands -> sanitizes halo garbage too
    return fminf(1.0f, fmaxf(-1.0f, v));
}

__global__ void init_kernel(const float* __restrict__ x) {
    int i = blockIdx.x * blockDim.x + threadIdx.x;
    if (i >= NN) return;
    g_yA[i] = x[i];
#pragma unroll
    for (int o = 0; o < 8; o++) g_W[o * NN + i] = 0.0f;
}

// Scatter edge weights into planar per-dst planes keyed by (dst-src) offset.
__global__ void scatter_W(const float* __restrict__ k,
                          const int* __restrict__ src,
                          const int* __restrict__ dst, int ne) {
    int e = blockIdx.x * blockDim.x + threadIdx.x;
    if (e >= ne) return;
    int j = src[e], i = dst[e];
    int dr = (i >> 10) - (j >> 10);      // pos(dst) - pos(src)
    int dc = (i & 1023) - (j & 1023);
    int idx = (dr + 1) * 3 + (dc + 1);   // 0..8, center (4) never occurs
    int o = (idx > 4) ? idx - 1 : idx;   // 0..7
    g_W[o * NN + i] = k[e];
}

// One stage for a 1x4 horizontal quad (points at p..p+3, lc % 4 == 0).
// smem holds act(u); own raw u + act(u) live in registers.
// Weight slot o (offset = dst-src) pairs with source neighbor at p - loff[o]:
// o0:(r+1,c+1) o1:(r+1,c) o2:(r+1,c-1) o3:(r,c+1) o4:(r,c-1)
// o5:(r-1,c+1) o6:(r-1,c) o7:(r-1,c-1)
// Active region shrinks with S: rows/cols [S, REG-S); bit S-1 of amask.
template<int S>
__device__ __forceinline__ void do_stage(
    const float* __restrict__ uc, float* __restrict__ un,
    unsigned amask, int p,
    const float w[4][8], float kk[4][5],
    float uu[4], float aa[4],
    const float yy[4], const float zz[4],
    const bool inn[4], const int gg[4],
    float* __restrict__ y_out, float* __restrict__ fin)
{
    if (!((amask >> (S - 1)) & 1u)) return;

    // 3x6 act-neighborhood: 14 loaded values + 4 own registers
    float4 tm = *(const float4*)(uc + p - REG);   // row-1, cols lc..lc+3
    float4 bm = *(const float4*)(uc + p + REG);   // row+1, cols lc..lc+3
    float tL = uc[p - REG - 1], tR = uc[p - REG + 4];
    float bL = uc[p + REG - 1], bR = uc[p + REG + 4];
    float mL = uc[p - 1],       mR = uc[p + 4];

    float s0 = zz[0] - uu[0];
    s0 = fmaf(w[0][0], bm.y,  s0); s0 = fmaf(w[0][1], bm.x,  s0);
    s0 = fmaf(w[0][2], bL,    s0); s0 = fmaf(w[0][3], aa[1], s0);
    s0 = fmaf(w[0][4], mL,    s0); s0 = fmaf(w[0][5], tm.y,  s0);
    s0 = fmaf(w[0][6], tm.x,  s0); s0 = fmaf(w[0][7], tL,    s0);

    float s1 = zz[1] - uu[1];
    s1 = fmaf(w[1][0], bm.z,  s1); s1 = fmaf(w[1][1], bm.y,  s1);
    s1 = fmaf(w[1][2], bm.x,  s1); s1 = fmaf(w[1][3], aa[2], s1);
    s1 = fmaf(w[1][4], aa[0], s1); s1 = fmaf(w[1][5], tm.z,  s1);
    s1 = fmaf(w[1][6], tm.y,  s1); s1 = fmaf(w[1][7], tm.x,  s1);

    float s2 = zz[2] - uu[2];
    s2 = fmaf(w[2][0], bm.w,  s2); s2 = fmaf(w[2][1], bm.z,  s2);
    s2 = fmaf(w[2][2], bm.y,  s2); s2 = fmaf(w[2][3], aa[3], s2);
    s2 = fmaf(w[2][4], aa[1], s2); s2 = fmaf(w[2][5], tm.w,  s2);
    s2 = fmaf(w[2][6], tm.z,  s2); s2 = fmaf(w[2][7], tm.y,  s2);

    float s3 = zz[3] - uu[3];
    s3 = fmaf(w[3][0], bR,    s3); s3 = fmaf(w[3][1], bm.w,  s3);
    s3 = fmaf(w[3][2], bm.z,  s3); s3 = fmaf(w[3][3], mR,    s3);
    s3 = fmaf(w[3][4], aa[2], s3); s3 = fmaf(w[3][5], tR,    s3);
    s3 = fmaf(w[3][6], tm.w,  s3); s3 = fmaf(w[3][7], tm.z,  s3);

    float s[4] = {s0, s1, s2, s3};

    if (S == 6) { // final B-combination -> global y (or clipped output)
#pragma unroll
        for (int q = 0; q < 4; q++) {
            if (inn[q]) {
                float yn = fmaf(DT, B1*kk[q][0] + B2*kk[q][1] + B3*kk[q][2]
                                  + B4*kk[q][3] + B5*kk[q][4] + B6*s[q], yy[q]);
                if (fin) fin[gg[q]] = fminf(1.0f, fmaxf(-1.0f, yn));
                else     y_out[gg[q]] = yn;
            }
        }
        return;
    }

#pragma unroll
    for (int q = 0; q < 4; q++) {
        float nu;
        if (S == 1)      { kk[q][0] = s[q]; nu = fmaf(DT, A21 * s[q], yy[q]); }
        else if (S == 2) { kk[q][1] = s[q]; nu = fmaf(DT, A31*kk[q][0] + A32*s[q], yy[q]); }
        else if (S == 3) { kk[q][2] = s[q]; nu = fmaf(DT, A41*kk[q][0] + A42*kk[q][1] + A43*s[q], yy[q]); }
        else if (S == 4) { kk[q][3] = s[q]; nu = fmaf(DT, A51*kk[q][0] + A52*kk[q][1] + A53*kk[q][2] + A54*s[q], yy[q]); }
        else             { kk[q][4] = s[q]; nu = fmaf(DT, A61*kk[q][0] + A62*kk[q][1] + A63*kk[q][2] + A64*kk[q][3] + A65*s[q], yy[q]); }
        uu[q] = nu;
        aa[q] = act(nu);
    }
    *(float4*)(un + p) = make_float4(aa[0], aa[1], aa[2], aa[3]);  // p % 4 == 0
}

// One full Tsit5 step for a 24x24 tile with halo-6 redundant compute;
// thread owns a 1x4 quad; active region shrinks by one ring per stage.
__global__ void __launch_bounds__(NTHR, 2)
step_kernel(int par, const float* __restrict__ z, float* __restrict__ fin) {
    __shared__ __align__(16) float sA_raw[SBUF];   // act(u) ping (+guards)
    __shared__ __align__(16) float sB_raw[SBUF];   // act(u) pong (+guards)
    float* const sA_buf = sA_raw + REG;
    float* const sB_buf = sB_raw + REG;

    const float* __restrict__ y_in  = par ? g_yB : g_yA;
    float*       __restrict__ y_out = par ? g_yA : g_yB;

    const int tid = threadIdx.x;
    const int r0 = (int)blockIdx.y * TS - H;
    const int c0 = (int)blockIdx.x * TS - H;

    // zero pong (incl. guards) + ping guards; fill ping body with act(y).
    for (int i = tid; i < SBUF; i += NTHR) sB_raw[i] = 0.0f;
    if (tid < REG) { sA_raw[tid] = 0.0f; sA_raw[SBUF - REG + tid] = 0.0f; }
    {
        // division-free walker: NTHR = 8*REG + 32
        int flr = tid / REG;
        int flc = tid - flr * REG;
        int pp = tid;
        while (pp < REG2) {
            int r = r0 + flr, c = c0 + flc;
            bool in = ((unsigned)r < NR) & ((unsigned)c < NC);
            sA_buf[pp] = in ? act(y_in[r * NC + c]) : 0.0f;
            pp += NTHR;
            flc += 32;
            if (flc >= REG) { flc -= REG; flr += 1; }
            flr += 8;
        }
    }

    // quad assignment: row lr in [1,35), cols lc..lc+3, lc = 4*qc
    const bool valid = tid < NQUAD;
    int qt = valid ? tid : 0;
    int qr = qt / NQR;
    int qc = qt - qr * NQR;
    int lr = 1 + qr;
    int lc = 4 * qc;            // 0,4,...,32
    int p  = lr * REG + lc;     // % 4 == 0 -> float4-aligned in smem

    // per-stage active mask (region [S, REG-S) in rows; cols intersect)
    unsigned amask = 0;
    if (valid) {
#pragma unroll
        for (int s = 1; s <= 6; s++)
            if ((lr >= s) & (lr < REG - s) & (lc + 3 >= s) & (lc <= REG - 1 - s))
                amask |= 1u << (s - 1);
    }

    int rA = r0 + lr;
    int cq = c0 + lc;           // col of point 0 (even; ≡2 mod 4)
    bool rowin = valid & ((unsigned)rA < NR);
    bool in[4];
    int gg[4];
#pragma unroll
    for (int q = 0; q < 4; q++) {
        int c = cq + q;
        in[q] = rowin & ((unsigned)c < NC);
        gg[q] = in[q] ? (rA * NC + c) : 0;
    }
    bool all4 = in[0] & in[3];
    int g0 = gg[0];             // even -> float2-aligned

    bool inn[4];
#pragma unroll
    for (int q = 0; q < 4; q++)
        inn[q] = in[q] & (lr >= H) & (lr < H + TS) & (lc + q >= H) & (lc + q < H + TS);

    float yy[4], zz[4], w[4][8];
    if (all4) {
        float2 y01 = *(const float2*)(y_in + g0);
        float2 y23 = *(const float2*)(y_in + g0 + 2);
        float2 z01 = *(const float2*)(z + g0);
        float2 z23 = *(const float2*)(z + g0 + 2);
        yy[0]=y01.x; yy[1]=y01.y; yy[2]=y23.x; yy[3]=y23.y;
        zz[0]=z01.x; zz[1]=z01.y; zz[2]=z23.x; zz[3]=z23.y;
#pragma unroll
        for (int o = 0; o < 8; o++) {
            const float* wp = g_W + (size_t)o * NN + g0;
            float2 w01 = *(const float2*)(wp);
            float2 w23 = *(const float2*)(wp + 2);
            w[0][o]=w01.x; w[1][o]=w01.y; w[2][o]=w23.x; w[3][o]=w23.y;
        }
    } else {
#pragma unroll
        for (int q = 0; q < 4; q++) {
            yy[q] = in[q] ? __ldg(y_in + gg[q]) : 0.0f;
            zz[q] = in[q] ? __ldg(z + gg[q])    : 0.0f;
#pragma unroll
            for (int o = 0; o < 8; o++)
                w[q][o] = in[q] ? g_W[(size_t)o * NN + gg[q]] : 0.0f;
        }
    }

    float uu[4], aa[4], kk[4][5];
#pragma unroll
    for (int q = 0; q < 4; q++) { uu[q] = yy[q]; aa[q] = act(yy[q]); }

    __syncthreads();

    do_stage<1>(sA_buf, sB_buf, amask, p, w, kk, uu, aa, yy, zz, inn, gg, y_out, fin);
    __syncthreads();
    do_stage<2>(sB_buf, sA_buf, amask, p, w, kk, uu, aa, yy, zz, inn, gg, y_out, fin);
    __syncthreads();
    do_stage<3>(sA_buf, sB_buf, amask, p, w, kk, uu, aa, yy, zz, inn, gg, y_out, fin);
    __syncthreads();
    do_stage<4>(sB_buf, sA_buf, amask, p, w, kk, uu, aa, yy, zz, inn, gg, y_out, fin);
    __syncthreads();
    do_stage<5>(sA_buf, sB_buf, amask, p, w, kk, uu, aa, yy, zz, inn, gg, y_out, fin);
    __syncthreads();
    do_stage<6>(sB_buf, sA_buf, amask, p, w, kk, uu, aa, yy, zz, inn, gg, y_out, fin);
}

extern "C" void kernel_launch(void* const* d_in, const int* in_sizes, int n_in,
                              void* d_out, int out_size) {
    const float* x   = (const float*)d_in[0];
    const float* z   = (const float*)d_in[1];
    const float* k   = (const float*)d_in[2];
    const int*   src = (const int*)d_in[3];
    const int*   dst = (const int*)d_in[4];
    int ne = in_sizes[2];

    init_kernel<<<(NN + 511) / 512, 512>>>(x);
    scatter_W<<<(ne + 511) / 512, 512>>>(k, src, dst, ne);

    dim3 grid(NTILE, NTILE);   // 43 x 43 tiles of 24x24
    for (int s = 0; s < 32; s++) {
        float* fin = (s == 31) ? (float*)d_out : nullptr;  // last step: fused clip -> d_out
        step_kernel<<<grid, NTHR>>>(s & 1, z, fin);
    }
}

// round 12
// speedup vs baseline: 1.3144x; 1.3144x over previous
#include <cuda_runtime.h>

#define NR 1024
#define NC 1024
#define NN (NR*NC)

#define TS   26              // output tile side
#define H    6               // halo (6 one-ring stages)
#define REG  38              // TS + 2*H (even)
#define REG2 (REG*REG)
#define NPR  19              // column-pairs per region row (even lc: 0..36)
#define NROWS 36             // region rows [1,37)
#define NPAIR (NPR*NROWS)    // 684
#define NTHR 704
#define NTILE ((NR + TS - 1) / TS)   // 40
#define SBUF (REG2 + 2*REG)  // guard space front/back (never zeroed; garbage ok)

// persistent scratch
__device__ float g_W[8 * NN];   // planar per-offset weights [o][i]
__device__ float g_yA[NN];
__device__ float g_yB[NN];

// Tsit5 coefficients
#define DT (1.0f/32.0f)
#define A21  0.161f
#define A31 -0.008480655492356989f
#define A32  0.335480655492357f
#define A41  2.8971530571054935f
#define A42 -6.359448489975075f
#define A43  4.3622954328695815f
#define A51  5.325864828439257f
#define A52 -11.748883564062828f
#define A53  7.4955393428898365f
#define A54 -0.09249506636175525f
#define A61  5.86145544294642f
#define A62 -12.92096931784711f
#define A63  8.159367898576159f
#define A64 -0.071584973281401f
#define A65 -0.028269050394068383f
#define B1   0.09646076681806523f
#define B2   0.01f
#define B3   0.4798896504144996f
#define B4   1.379008574103742f
#define B5  -3.290069515436081f
#define B6   2.324710524099774f

__device__ __forceinline__ float act(float v) {
    // fmaxf/fminf drop NaN operands -> sanitizes halo/guard garbage too
    return fminf(1.0f, fmaxf(-1.0f, v));
}

__global__ void init_kernel(const float* __restrict__ x) {
    int i = blockIdx.x * blockDim.x + threadIdx.x;
    if (i >= NN) return;
    g_yA[i] = x[i];
#pragma unroll
    for (int o = 0; o < 8; o++) g_W[o * NN + i] = 0.0f;
}

// Scatter edge weights into planar per-dst planes keyed by (dst-src) offset.
__global__ void scatter_W(const float* __restrict__ k,
                          const int* __restrict__ src,
                          const int* __restrict__ dst, int ne) {
    int e = blockIdx.x * blockDim.x + threadIdx.x;
    if (e >= ne) return;
    int j = src[e], i = dst[e];
    int dr = (i >> 10) - (j >> 10);      // pos(dst) - pos(src)
    int dc = (i & 1023) - (j & 1023);
    int idx = (dr + 1) * 3 + (dc + 1);   // 0..8, center (4) never occurs
    int o = (idx > 4) ? idx - 1 : idx;   // 0..7
    g_W[o * NN + i] = k[e];
}

// One stage for a horizontally-adjacent point pair (A at p, B at p+1), lc even.
// smem holds act(u); raw u + act(u) of own points live in registers.
// Weight slot o (offset = dst-src) pairs with source neighbor at p - loff[o]:
// o0:(r+1,c+1) o1:(r+1,c) o2:(r+1,c-1) o3:(r,c+1) o4:(r,c-1)
// o5:(r-1,c+1) o6:(r-1,c) o7:(r-1,c-1)
// Active region shrinks with S: rows/cols [S, REG-S); bit S-1 of amask.
template<int S>
__device__ __forceinline__ void do_stage(
    const float* __restrict__ uc, float* __restrict__ un,
    unsigned amask, int p,
    const float wA[8], const float wB[8],
    float kA[5], float kB[5],
    float& uAc, float& uBc, float& aAc, float& aBc,
    float yA, float yB, float zA, float zB,
    int gA,
    float* __restrict__ y_out, float* __restrict__ fin)
{
    if (!((amask >> (S - 1)) & 1u)) return;

    // pre-activated neighbors (lc even: float2 at p-REG / p+REG aligned)
    float2 am = *(const float2*)(uc + p - REG);      // row-1, cols lc,lc+1
    float2 ap = *(const float2*)(uc + p + REG);      // row+1, cols lc,lc+1
    float  amL = uc[p - REG - 1];                    // row-1, col lc-1
    float  amR = uc[p - REG + 2];                    // row-1, col lc+2
    float  apL = uc[p + REG - 1];                    // row+1, col lc-1
    float  apR = uc[p + REG + 2];                    // row+1, col lc+2
    float  lA  = uc[p - 1];                          // row  , col lc-1
    float  rB  = uc[p + 2];                          // row  , col lc+2

    // Point A (center p): s = z - u + sum_o w[o] * act(u[p - loff[o]])
    float sA = zA - uAc;
    sA = fmaf(wA[0], ap.y, sA);   // src p+REG+1
    sA = fmaf(wA[1], ap.x, sA);   // p+REG
    sA = fmaf(wA[2], apL,  sA);   // p+REG-1
    sA = fmaf(wA[3], aBc,  sA);   // p+1  (own pair partner, in-register)
    sA = fmaf(wA[4], lA,   sA);   // p-1
    sA = fmaf(wA[5], am.y, sA);   // p-REG+1
    sA = fmaf(wA[6], am.x, sA);   // p-REG
    sA = fmaf(wA[7], amL,  sA);   // p-REG-1

    // Point B (center p+1)
    float sB = zB - uBc;
    sB = fmaf(wB[0], apR,  sB);   // p+REG+2
    sB = fmaf(wB[1], ap.y, sB);   // p+REG+1
    sB = fmaf(wB[2], ap.x, sB);   // p+REG
    sB = fmaf(wB[3], rB,   sB);   // p+2
    sB = fmaf(wB[4], aAc,  sB);   // p    (own pair partner, in-register)
    sB = fmaf(wB[5], amR,  sB);   // p-REG+2
    sB = fmaf(wB[6], am.y, sB);   // p-REG+1
    sB = fmaf(wB[7], am.x, sB);   // p-REG

    if (S == 6) { // final B-combination -> global y (or clipped output)
        if ((amask >> 6) & 1u) {   // innA
            float yn = fmaf(DT, B1*kA[0] + B2*kA[1] + B3*kA[2]
                              + B4*kA[3] + B5*kA[4] + B6*sA, yA);
            if (fin) fin[gA] = fminf(1.0f, fmaxf(-1.0f, yn));
            else     y_out[gA] = yn;
        }
        if ((amask >> 7) & 1u) {   // innB
            float yn = fmaf(DT, B1*kB[0] + B2*kB[1] + B3*kB[2]
                              + B4*kB[3] + B5*kB[4] + B6*sB, yB);
            if (fin) fin[gA + 1] = fminf(1.0f, fmaxf(-1.0f, yn));
            else     y_out[gA + 1] = yn;
        }
        return;
    }

    float nuA, nuB;
    if (S == 1) {
        kA[0] = sA; kB[0] = sB;
        nuA = fmaf(DT, A21 * sA, yA);
        nuB = fmaf(DT, A21 * sB, yB);
    } else if (S == 2) {
        kA[1] = sA; kB[1] = sB;
        nuA = fmaf(DT, A31*kA[0] + A32*sA, yA);
        nuB = fmaf(DT, A31*kB[0] + A32*sB, yB);
    } else if (S == 3) {
        kA[2] = sA; kB[2] = sB;
        nuA = fmaf(DT, A41*kA[0] + A42*kA[1] + A43*sA, yA);
        nuB = fmaf(DT, A41*kB[0] + A42*kB[1] + A43*sB, yB);
    } else if (S == 4) {
        kA[3] = sA; kB[3] = sB;
        nuA = fmaf(DT, A51*kA[0] + A52*kA[1] + A53*kA[2] + A54*sA, yA);
        nuB = fmaf(DT, A51*kB[0] + A52*kB[1] + A53*kB[2] + A54*sB, yB);
    } else { // S == 5
        kA[4] = sA; kB[4] = sB;
        nuA = fmaf(DT, A61*kA[0] + A62*kA[1] + A63*kA[2] + A64*kA[3] + A65*sA, yA);
        nuB = fmaf(DT, A61*kB[0] + A62*kB[1] + A63*kB[2] + A64*kB[3] + A65*sB, yB);
    }
    uAc = nuA;  aAc = act(nuA);
    uBc = nuB;  aBc = act(nuB);
    *(float2*)(un + p) = make_float2(aAc, aBc);   // p even -> aligned
}

// One full Tsit5 step for a 26x26 tile with halo-6 redundant compute;
// active region shrinks by one ring per stage. No pong/guard zeroing needed:
// stage s+1's read set is contained in stage s's written set by construction.
__global__ void __launch_bounds__(NTHR, 2)
step_kernel(int par, const float* __restrict__ z, float* __restrict__ fin) {
    __shared__ __align__(16) float sA_raw[SBUF];   // act(u) ping (+guard space)
    __shared__ __align__(16) float sB_raw[SBUF];   // act(u) pong (+guard space)
    float* const sA_buf = sA_raw + REG;
    float* const sB_buf = sB_raw + REG;

    const float* __restrict__ y_in  = par ? g_yB : g_yA;
    float*       __restrict__ y_out = par ? g_yA : g_yB;

    const int tid = threadIdx.x;
    const int r0 = (int)blockIdx.y * TS - H;
    const int c0 = (int)blockIdx.x * TS - H;

    // fill ping body with act(y) (zero-padded OOB), division-free walker.
    // NTHR = 18*REG + 20 => per iteration: flr += 18, flc += 20 (with wrap).
    {
        int flr = tid / REG;
        int flc = tid - flr * REG;
        int pp = tid;
        while (pp < REG2) {
            int r = r0 + flr, c = c0 + flc;
            bool in = ((unsigned)r < NR) & ((unsigned)c < NC);
            sA_buf[pp] = in ? act(y_in[r * NC + c]) : 0.0f;
            pp += NTHR;
            flc += 20;
            if (flc >= REG) { flc -= REG; flr += 1; }
            flr += 18;
        }
    }

    // per-thread pair assignment: row lr in [1,37), cols (lc, lc+1), lc EVEN
    const bool valid = tid < NPAIR;
    int qt = valid ? tid : 0;
    int pr = qt / NPR;
    int pc = qt - pr * NPR;
    int lr = 1 + pr;
    int lc = 2 * pc;            // 0,2,...,36
    int p  = lr * REG + lc;

    int rA = r0 + lr, cA = c0 + lc, cB = cA + 1;
    bool inA = valid & ((unsigned)rA < NR) & ((unsigned)cA < NC);
    bool inB = valid & ((unsigned)rA < NR) & ((unsigned)cB < NC);
    int gA = inA ? (rA * NC + cA) : (inB ? (rA * NC + cB) - 1 : 0);
    bool inAB = inA & inB;      // pair-vector loads need both (gA even, aligned)

    // amask: bits 0..5 = stage 1..6 active; bit 6 = innA, bit 7 = innB
    unsigned amask = 0;
    if (valid) {
#pragma unroll
        for (int s = 1; s <= 6; s++)
            if ((lr >= s) & (lr < REG - s) & (lc + 1 >= s) & (lc <= REG - 1 - s))
                amask |= 1u << (s - 1);
        if (inA & (lr >= H) & (lr < H + TS) & (lc   >= H) & (lc   < H + TS)) amask |= 1u << 6;
        if (inB & (lr >= H) & (lr < H + TS) & (lc+1 >= H) & (lc+1 < H + TS)) amask |= 1u << 7;
    }

    float zA, zB, yA, yB;
    if (inAB) {
        float2 zv = *(const float2*)(z + gA);
        float2 yv = *(const float2*)(y_in + gA);
        zA = zv.x; zB = zv.y; yA = yv.x; yB = yv.y;
    } else {
        zA = inA ? __ldg(&z[gA]) : 0.0f;
        zB = inB ? __ldg(&z[gA + 1]) : 0.0f;
        yA = inA ? __ldg(&y_in[gA]) : 0.0f;
        yB = inB ? __ldg(&y_in[gA + 1]) : 0.0f;
    }

    float wA[8], wB[8];
    if (inAB) {
#pragma unroll
        for (int o = 0; o < 8; o++) {
            float2 wv = *(const float2*)(g_W + (size_t)o * NN + gA);
            wA[o] = wv.x; wB[o] = wv.y;
        }
    } else {
#pragma unroll
        for (int o = 0; o < 8; o++) {
            wA[o] = inA ? g_W[(size_t)o * NN + gA] : 0.0f;
            wB[o] = inB ? g_W[(size_t)o * NN + gA + 1] : 0.0f;
        }
    }

    float uAc = yA, uBc = yB;
    float aAc = act(yA), aBc = act(yB);
    float kA[5], kB[5];

    __syncthreads();

    do_stage<1>(sA_buf, sB_buf, amask, p, wA, wB, kA, kB, uAc, uBc, aAc, aBc,
                yA, yB, zA, zB, gA, y_out, fin);
    __syncthreads();
    do_stage<2>(sB_buf, sA_buf, amask, p, wA, wB, kA, kB, uAc, uBc, aAc, aBc,
                yA, yB, zA, zB, gA, y_out, fin);
    __syncthreads();
    do_stage<3>(sA_buf, sB_buf, amask, p, wA, wB, kA, kB, uAc, uBc, aAc, aBc,
                yA, yB, zA, zB, gA, y_out, fin);
    __syncthreads();
    do_stage<4>(sB_buf, sA_buf, amask, p, wA, wB, kA, kB, uAc, uBc, aAc, aBc,
                yA, yB, zA, zB, gA, y_out, fin);
    __syncthreads();
    do_stage<5>(sA_buf, sB_buf, amask, p, wA, wB, kA, kB, uAc, uBc, aAc, aBc,
                yA, yB, zA, zB, gA, y_out, fin);
    __syncthreads();
    do_stage<6>(sB_buf, sA_buf, amask, p, wA, wB, kA, kB, uAc, uBc, aAc, aBc,
                yA, yB, zA, zB, gA, y_out, fin);
}

extern "C" void kernel_launch(void* const* d_in, const int* in_sizes, int n_in,
                              void* d_out, int out_size) {
    const float* x   = (const float*)d_in[0];
    const float* z   = (const float*)d_in[1];
    const float* k   = (const float*)d_in[2];
    const int*   src = (const int*)d_in[3];
    const int*   dst = (const int*)d_in[4];
    int ne = in_sizes[2];

    init_kernel<<<(NN + 511) / 512, 512>>>(x);
    scatter_W<<<(ne + 511) / 512, 512>>>(k, src, dst, ne);

    dim3 grid(NTILE, NTILE);   // 40 x 40 tiles of 26x26
    for (int s = 0; s < 32; s++) {
        float* fin = (s == 31) ? (float*)d_out : nullptr;  // last step: fused clip -> d_out
        step_kernel<<<grid, NTHR>>>(s & 1, z, fin);
    }
}

// round 13
// speedup vs baseline: 1.3716x; 1.0436x over previous
#include <cuda_runtime.h>

#define NR 1024
#define NC 1024
#define NN (NR*NC)

#define TS   28              // output tile side
#define H    6               // halo (6 one-ring stages)
#define REG  40              // TS + 2*H (even)
#define REG2 (REG*REG)
#define NPR  20              // column-pairs per region row (even lc: 0..38)
#define NROWS 38             // region rows [1,39)
#define NPAIR (NPR*NROWS)    // 760
#define NTHR 768
#define NTILE ((NR + TS - 1) / TS)   // 37
#define SBUF (REG2 + 2*REG)  // guard space front/back (never zeroed; garbage ok)

// persistent scratch
__device__ float g_W[8 * NN];   // planar per-offset weights [o][i]
__device__ float g_yA[NN];
__device__ float g_yB[NN];

// Tsit5 coefficients
#define DT (1.0f/32.0f)
#define A21  0.161f
#define A31 -0.008480655492356989f
#define A32  0.335480655492357f
#define A41  2.8971530571054935f
#define A42 -6.359448489975075f
#define A43  4.3622954328695815f
#define A51  5.325864828439257f
#define A52 -11.748883564062828f
#define A53  7.4955393428898365f
#define A54 -0.09249506636175525f
#define A61  5.86145544294642f
#define A62 -12.92096931784711f
#define A63  8.159367898576159f
#define A64 -0.071584973281401f
#define A65 -0.028269050394068383f
#define B1   0.09646076681806523f
#define B2   0.01f
#define B3   0.4798896504144996f
#define B4   1.379008574103742f
#define B5  -3.290069515436081f
#define B6   2.324710524099774f

__device__ __forceinline__ float act(float v) {
    // fmaxf/fminf drop NaN operands -> sanitizes halo/guard garbage too
    return fminf(1.0f, fmaxf(-1.0f, v));
}

__global__ void init_kernel(const float* __restrict__ x) {
    int i = blockIdx.x * blockDim.x + threadIdx.x;
    if (i >= NN) return;
    g_yA[i] = x[i];
#pragma unroll
    for (int o = 0; o < 8; o++) g_W[o * NN + i] = 0.0f;
}

// Scatter edge weights into planar per-dst planes keyed by (dst-src) offset.
__global__ void scatter_W(const float* __restrict__ k,
                          const int* __restrict__ src,
                          const int* __restrict__ dst, int ne) {
    int e = blockIdx.x * blockDim.x + threadIdx.x;
    if (e >= ne) return;
    int j = src[e], i = dst[e];
    int dr = (i >> 10) - (j >> 10);      // pos(dst) - pos(src)
    int dc = (i & 1023) - (j & 1023);
    int idx = (dr + 1) * 3 + (dc + 1);   // 0..8, center (4) never occurs
    int o = (idx > 4) ? idx - 1 : idx;   // 0..7
    g_W[o * NN + i] = k[e];
}

// One stage for a horizontally-adjacent point pair (A at p, B at p+1), lc even.
// smem holds act(u); raw u + act(u) of own points live in registers.
// Weight slot o (offset = dst-src) pairs with source neighbor at p - loff[o]:
// o0:(r+1,c+1) o1:(r+1,c) o2:(r+1,c-1) o3:(r,c+1) o4:(r,c-1)
// o5:(r-1,c+1) o6:(r-1,c) o7:(r-1,c-1)
// Active region shrinks with S: rows/cols [S, REG-S); bit S-1 of amask.
template<int S>
__device__ __forceinline__ void do_stage(
    const float* __restrict__ uc, float* __restrict__ un,
    unsigned amask, int p,
    const float wA[8], const float wB[8],
    float kA[5], float kB[5],
    float& uAc, float& uBc, float& aAc, float& aBc,
    float yA, float yB, float zA, float zB,
    int gA,
    float* __restrict__ y_out, float* __restrict__ fin)
{
    if (!((amask >> (S - 1)) & 1u)) return;

    // pre-activated neighbors (lc even: float2 at p-REG / p+REG aligned)
    float2 am = *(const float2*)(uc + p - REG);      // row-1, cols lc,lc+1
    float2 ap = *(const float2*)(uc + p + REG);      // row+1, cols lc,lc+1
    float  amL = uc[p - REG - 1];                    // row-1, col lc-1
    float  amR = uc[p - REG + 2];                    // row-1, col lc+2
    float  apL = uc[p + REG - 1];                    // row+1, col lc-1
    float  apR = uc[p + REG + 2];                    // row+1, col lc+2
    float  lA  = uc[p - 1];                          // row  , col lc-1
    float  rB  = uc[p + 2];                          // row  , col lc+2

    // Point A (center p): s = z - u + sum_o w[o] * act(u[p - loff[o]])
    float sA = zA - uAc;
    sA = fmaf(wA[0], ap.y, sA);   // src p+REG+1
    sA = fmaf(wA[1], ap.x, sA);   // p+REG
    sA = fmaf(wA[2], apL,  sA);   // p+REG-1
    sA = fmaf(wA[3], aBc,  sA);   // p+1  (own pair partner, in-register)
    sA = fmaf(wA[4], lA,   sA);   // p-1
    sA = fmaf(wA[5], am.y, sA);   // p-REG+1
    sA = fmaf(wA[6], am.x, sA);   // p-REG
    sA = fmaf(wA[7], amL,  sA);   // p-REG-1

    // Point B (center p+1)
    float sB = zB - uBc;
    sB = fmaf(wB[0], apR,  sB);   // p+REG+2
    sB = fmaf(wB[1], ap.y, sB);   // p+REG+1
    sB = fmaf(wB[2], ap.x, sB);   // p+REG
    sB = fmaf(wB[3], rB,   sB);   // p+2
    sB = fmaf(wB[4], aAc,  sB);   // p    (own pair partner, in-register)
    sB = fmaf(wB[5], amR,  sB);   // p-REG+2
    sB = fmaf(wB[6], am.y, sB);   // p-REG+1
    sB = fmaf(wB[7], am.x, sB);   // p-REG

    if (S == 6) { // final B-combination -> global y (or clipped output)
        if ((amask >> 6) & 1u) {   // innA
            float yn = fmaf(DT, B1*kA[0] + B2*kA[1] + B3*kA[2]
                              + B4*kA[3] + B5*kA[4] + B6*sA, yA);
            if (fin) fin[gA] = fminf(1.0f, fmaxf(-1.0f, yn));
            else     y_out[gA] = yn;
        }
        if ((amask >> 7) & 1u) {   // innB
            float yn = fmaf(DT, B1*kB[0] + B2*kB[1] + B3*kB[2]
                              + B4*kB[3] + B5*kB[4] + B6*sB, yB);
            if (fin) fin[gA + 1] = fminf(1.0f, fmaxf(-1.0f, yn));
            else     y_out[gA + 1] = yn;
        }
        return;
    }

    float nuA, nuB;
    if (S == 1) {
        kA[0] = sA; kB[0] = sB;
        nuA = fmaf(DT, A21 * sA, yA);
        nuB = fmaf(DT, A21 * sB, yB);
    } else if (S == 2) {
        kA[1] = sA; kB[1] = sB;
        nuA = fmaf(DT, A31*kA[0] + A32*sA, yA);
        nuB = fmaf(DT, A31*kB[0] + A32*sB, yB);
    } else if (S == 3) {
        kA[2] = sA; kB[2] = sB;
        nuA = fmaf(DT, A41*kA[0] + A42*kA[1] + A43*sA, yA);
        nuB = fmaf(DT, A41*kB[0] + A42*kB[1] + A43*sB, yB);
    } else if (S == 4) {
        kA[3] = sA; kB[3] = sB;
        nuA = fmaf(DT, A51*kA[0] + A52*kA[1] + A53*kA[2] + A54*sA, yA);
        nuB = fmaf(DT, A51*kB[0] + A52*kB[1] + A53*kB[2] + A54*sB, yB);
    } else { // S == 5
        kA[4] = sA; kB[4] = sB;
        nuA = fmaf(DT, A61*kA[0] + A62*kA[1] + A63*kA[2] + A64*kA[3] + A65*sA, yA);
        nuB = fmaf(DT, A61*kB[0] + A62*kB[1] + A63*kB[2] + A64*kB[3] + A65*sB, yB);
    }
    uAc = nuA;  aAc = act(nuA);
    uBc = nuB;  aBc = act(nuB);
    *(float2*)(un + p) = make_float2(aAc, aBc);   // p even -> aligned
}

// One full Tsit5 step for a 28x28 tile with halo-6 redundant compute;
// active region shrinks by one ring per stage. No pong/guard zeroing needed:
// stage s+1's read set is contained in stage s's written set by construction.
__global__ void __launch_bounds__(NTHR, 2)
step_kernel(int par, const float* __restrict__ z, float* __restrict__ fin) {
    __shared__ __align__(16) float sA_raw[SBUF];   // act(u) ping (+guard space)
    __shared__ __align__(16) float sB_raw[SBUF];   // act(u) pong (+guard space)
    float* const sA_buf = sA_raw + REG;
    float* const sB_buf = sB_raw + REG;

    const float* __restrict__ y_in  = par ? g_yB : g_yA;
    float*       __restrict__ y_out = par ? g_yA : g_yB;

    const int tid = threadIdx.x;
    const int r0 = (int)blockIdx.y * TS - H;
    const int c0 = (int)blockIdx.x * TS - H;

    // fill ping body with act(y) (zero-padded OOB), division-free walker.
    // NTHR = 19*REG + 8 => per iteration: flr += 19, flc += 8 (with wrap).
    {
        int flr = tid / REG;
        int flc = tid - flr * REG;
        int pp = tid;
        while (pp < REG2) {
            int r = r0 + flr, c = c0 + flc;
            bool in = ((unsigned)r < NR) & ((unsigned)c < NC);
            sA_buf[pp] = in ? act(y_in[r * NC + c]) : 0.0f;
            pp += NTHR;
            flc += 8;
            if (flc >= REG) { flc -= REG; flr += 1; }
            flr += 19;
        }
    }

    // per-thread pair assignment: row lr in [1,39), cols (lc, lc+1), lc EVEN
    const bool valid = tid < NPAIR;
    int qt = valid ? tid : 0;
    int pr = qt / NPR;
    int pc = qt - pr * NPR;
    int lr = 1 + pr;
    int lc = 2 * pc;            // 0,2,...,38
    int p  = lr * REG + lc;

    int rA = r0 + lr, cA = c0 + lc, cB = cA + 1;
    bool inA = valid & ((unsigned)rA < NR) & ((unsigned)cA < NC);
    bool inB = valid & ((unsigned)rA < NR) & ((unsigned)cB < NC);
    int gA = inA ? (rA * NC + cA) : (inB ? (rA * NC + cB) - 1 : 0);
    bool inAB = inA & inB;      // pair-vector loads need both (gA even, aligned)

    // amask: bits 0..5 = stage 1..6 active; bit 6 = innA, bit 7 = innB
    unsigned amask = 0;
    if (valid) {
#pragma unroll
        for (int s = 1; s <= 6; s++)
            if ((lr >= s) & (lr < REG - s) & (lc + 1 >= s) & (lc <= REG - 1 - s))
                amask |= 1u << (s - 1);
        if (inA & (lr >= H) & (lr < H + TS) & (lc   >= H) & (lc   < H + TS)) amask |= 1u << 6;
        if (inB & (lr >= H) & (lr < H + TS) & (lc+1 >= H) & (lc+1 < H + TS)) amask |= 1u << 7;
    }

    float zA, zB, yA, yB;
    if (inAB) {
        float2 zv = *(const float2*)(z + gA);
        float2 yv = *(const float2*)(y_in + gA);
        zA = zv.x; zB = zv.y; yA = yv.x; yB = yv.y;
    } else {
        zA = inA ? __ldg(&z[gA]) : 0.0f;
        zB = inB ? __ldg(&z[gA + 1]) : 0.0f;
        yA = inA ? __ldg(&y_in[gA]) : 0.0f;
        yB = inB ? __ldg(&y_in[gA + 1]) : 0.0f;
    }

    float wA[8], wB[8];
    if (inAB) {
#pragma unroll
        for (int o = 0; o < 8; o++) {
            float2 wv = *(const float2*)(g_W + (size_t)o * NN + gA);
            wA[o] = wv.x; wB[o] = wv.y;
        }
    } else {
#pragma unroll
        for (int o = 0; o < 8; o++) {
            wA[o] = inA ? g_W[(size_t)o * NN + gA] : 0.0f;
            wB[o] = inB ? g_W[(size_t)o * NN + gA + 1] : 0.0f;
        }
    }

    float uAc = yA, uBc = yB;
    float aAc = act(yA), aBc = act(yB);
    float kA[5], kB[5];

    __syncthreads();

    do_stage<1>(sA_buf, sB_buf, amask, p, wA, wB, kA, kB, uAc, uBc, aAc, aBc,
                yA, yB, zA, zB, gA, y_out, fin);
    __syncthreads();
    do_stage<2>(sB_buf, sA_buf, amask, p, wA, wB, kA, kB, uAc, uBc, aAc, aBc,
                yA, yB, zA, zB, gA, y_out, fin);
    __syncthreads();
    do_stage<3>(sA_buf, sB_buf, amask, p, wA, wB, kA, kB, uAc, uBc, aAc, aBc,
                yA, yB, zA, zB, gA, y_out, fin);
    __syncthreads();
    do_stage<4>(sB_buf, sA_buf, amask, p, wA, wB, kA, kB, uAc, uBc, aAc, aBc,
                yA, yB, zA, zB, gA, y_out, fin);
    __syncthreads();
    do_stage<5>(sA_buf, sB_buf, amask, p, wA, wB, kA, kB, uAc, uBc, aAc, aBc,
                yA, yB, zA, zB, gA, y_out, fin);
    __syncthreads();
    do_stage<6>(sB_buf, sA_buf, amask, p, wA, wB, kA, kB, uAc, uBc, aAc, aBc,
                yA, yB, zA, zB, gA, y_out, fin);
}

extern "C" void kernel_launch(void* const* d_in, const int* in_sizes, int n_in,
                              void* d_out, int out_size) {
    const float* x   = (const float*)d_in[0];
    const float* z   = (const float*)d_in[1];
    const float* k   = (const float*)d_in[2];
    const int*   src = (const int*)d_in[3];
    const int*   dst = (const int*)d_in[4];
    int ne = in_sizes[2];

    init_kernel<<<(NN + 511) / 512, 512>>>(x);
    scatter_W<<<(ne + 511) / 512, 512>>>(k, src, dst, ne);

    dim3 grid(NTILE, NTILE);   // 37 x 37 tiles of 28x28
    for (int s = 0; s < 32; s++) {
        float* fin = (s == 31) ? (float*)d_out : nullptr;  // last step: fused clip -> d_out
        step_kernel<<<grid, NTHR>>>(s & 1, z, fin);
    }
}

// round 14
// speedup vs baseline: 1.3922x; 1.0150x over previous
#include <cuda_runtime.h>

#define NR 1024
#define NC 1024
#define NN (NR*NC)

#define TS   28              // output tile side
#define H    6               // halo (6 one-ring stages)
#define REG  40              // TS + 2*H (even)
#define REG2 (REG*REG)
#define NPR  20              // column-pairs per region row (even lc: 0..38)
#define NROWS 38             // region rows [1,39)
#define NPAIR (NPR*NROWS)    // 760
#define NTHR 768
#define NTILE ((NR + TS - 1) / TS)   // 37
#define SBUF (REG2 + 2*REG)  // guard space front/back (never zeroed; garbage ok)

// persistent scratch
__device__ float g_W[8 * NN];   // planar per-offset weights [o][i]
__device__ float g_yA[NN];
__device__ float g_yB[NN];

// Tsit5 coefficients
#define DT (1.0f/32.0f)
#define A21  0.161f
#define A31 -0.008480655492356989f
#define A32  0.335480655492357f
#define A41  2.8971530571054935f
#define A42 -6.359448489975075f
#define A43  4.3622954328695815f
#define A51  5.325864828439257f
#define A52 -11.748883564062828f
#define A53  7.4955393428898365f
#define A54 -0.09249506636175525f
#define A61  5.86145544294642f
#define A62 -12.92096931784711f
#define A63  8.159367898576159f
#define A64 -0.071584973281401f
#define A65 -0.028269050394068383f
#define B1   0.09646076681806523f
#define B2   0.01f
#define B3   0.4798896504144996f
#define B4   1.379008574103742f
#define B5  -3.290069515436081f
#define B6   2.324710524099774f

__device__ __forceinline__ float act(float v) {
    // fmaxf/fminf drop NaN operands -> sanitizes halo/guard garbage too
    return fminf(1.0f, fmaxf(-1.0f, v));
}

__global__ void init_kernel(const float* __restrict__ x) {
    int i = blockIdx.x * blockDim.x + threadIdx.x;
    if (i >= NN) return;
    g_yA[i] = x[i];
#pragma unroll
    for (int o = 0; o < 8; o++) g_W[o * NN + i] = 0.0f;
}

// Scatter edge weights into planar per-dst planes keyed by (dst-src) offset.
__global__ void scatter_W(const float* __restrict__ k,
                          const int* __restrict__ src,
                          const int* __restrict__ dst, int ne) {
    int e = blockIdx.x * blockDim.x + threadIdx.x;
    if (e >= ne) return;
    int j = src[e], i = dst[e];
    int dr = (i >> 10) - (j >> 10);      // pos(dst) - pos(src)
    int dc = (i & 1023) - (j & 1023);
    int idx = (dr + 1) * 3 + (dc + 1);   // 0..8, center (4) never occurs
    int o = (idx > 4) ? idx - 1 : idx;   // 0..7
    g_W[o * NN + i] = k[e];
}

// One stage for a horizontally-adjacent point pair (A at p, B at p+1), lc even.
// smem holds act(u); raw u + act(u) of own points live in registers.
// Weight slot o (offset = dst-src) pairs with source neighbor at p - loff[o]:
// o0:(r+1,c+1) o1:(r+1,c) o2:(r+1,c-1) o3:(r,c+1) o4:(r,c-1)
// o5:(r-1,c+1) o6:(r-1,c) o7:(r-1,c-1)
// Active region shrinks with S: rows/cols [S, REG-S); active iff S <= smax.
template<int S>
__device__ __forceinline__ void do_stage(
    const float* __restrict__ uc, float* __restrict__ un,
    int smax, int p,
    const float wA[8], const float wB[8],
    float kA[5], float kB[5],
    float& uAc, float& uBc, float& aAc, float& aBc,
    float yA, float yB, float zA, float zB,
    bool innA, bool innB, int gA,
    float* __restrict__ y_out, float* __restrict__ fin)
{
    if (S > smax) return;

    // pre-activated neighbors (lc even: float2 at p-REG / p+REG aligned)
    float2 am = *(const float2*)(uc + p - REG);      // row-1, cols lc,lc+1
    float2 ap = *(const float2*)(uc + p + REG);      // row+1, cols lc,lc+1
    float  amL = uc[p - REG - 1];                    // row-1, col lc-1
    float  amR = uc[p - REG + 2];                    // row-1, col lc+2
    float  apL = uc[p + REG - 1];                    // row+1, col lc-1
    float  apR = uc[p + REG + 2];                    // row+1, col lc+2
    float  lA  = uc[p - 1];                          // row  , col lc-1
    float  rB  = uc[p + 2];                          // row  , col lc+2

    // Point A (center p): s = z - u + sum_o w[o] * act(u[p - loff[o]])
    float sA = zA - uAc;
    sA = fmaf(wA[0], ap.y, sA);   // src p+REG+1
    sA = fmaf(wA[1], ap.x, sA);   // p+REG
    sA = fmaf(wA[2], apL,  sA);   // p+REG-1
    sA = fmaf(wA[3], aBc,  sA);   // p+1  (own pair partner, in-register)
    sA = fmaf(wA[4], lA,   sA);   // p-1
    sA = fmaf(wA[5], am.y, sA);   // p-REG+1
    sA = fmaf(wA[6], am.x, sA);   // p-REG
    sA = fmaf(wA[7], amL,  sA);   // p-REG-1

    // Point B (center p+1)
    float sB = zB - uBc;
    sB = fmaf(wB[0], apR,  sB);   // p+REG+2
    sB = fmaf(wB[1], ap.y, sB);   // p+REG+1
    sB = fmaf(wB[2], ap.x, sB);   // p+REG
    sB = fmaf(wB[3], rB,   sB);   // p+2
    sB = fmaf(wB[4], aAc,  sB);   // p    (own pair partner, in-register)
    sB = fmaf(wB[5], amR,  sB);   // p-REG+2
    sB = fmaf(wB[6], am.y, sB);   // p-REG+1
    sB = fmaf(wB[7], am.x, sB);   // p-REG

    if (S == 6) { // final B-combination -> global y (or clipped output)
        if (innA) {
            float yn = fmaf(DT, B1*kA[0] + B2*kA[1] + B3*kA[2]
                              + B4*kA[3] + B5*kA[4] + B6*sA, yA);
            if (fin) fin[gA] = fminf(1.0f, fmaxf(-1.0f, yn));
            else     y_out[gA] = yn;
        }
        if (innB) {
            float yn = fmaf(DT, B1*kB[0] + B2*kB[1] + B3*kB[2]
                              + B4*kB[3] + B5*kB[4] + B6*sB, yB);
            if (fin) fin[gA + 1] = fminf(1.0f, fmaxf(-1.0f, yn));
            else     y_out[gA + 1] = yn;
        }
        return;
    }

    float nuA, nuB;
    if (S == 1) {
        kA[0] = sA; kB[0] = sB;
        nuA = fmaf(DT, A21 * sA, yA);
        nuB = fmaf(DT, A21 * sB, yB);
    } else if (S == 2) {
        kA[1] = sA; kB[1] = sB;
        nuA = fmaf(DT, A31*kA[0] + A32*sA, yA);
        nuB = fmaf(DT, A31*kB[0] + A32*sB, yB);
    } else if (S == 3) {
        kA[2] = sA; kB[2] = sB;
        nuA = fmaf(DT, A41*kA[0] + A42*kA[1] + A43*sA, yA);
        nuB = fmaf(DT, A41*kB[0] + A42*kB[1] + A43*sB, yB);
    } else if (S == 4) {
        kA[3] = sA; kB[3] = sB;
        nuA = fmaf(DT, A51*kA[0] + A52*kA[1] + A53*kA[2] + A54*sA, yA);
        nuB = fmaf(DT, A51*kB[0] + A52*kB[1] + A53*kB[2] + A54*sB, yB);
    } else { // S == 5
        kA[4] = sA; kB[4] = sB;
        nuA = fmaf(DT, A61*kA[0] + A62*kA[1] + A63*kA[2] + A64*kA[3] + A65*sA, yA);
        nuB = fmaf(DT, A61*kB[0] + A62*kB[1] + A63*kB[2] + A64*kB[3] + A65*sB, yB);
    }
    uAc = nuA;  aAc = act(nuA);
    uBc = nuB;  aBc = act(nuB);
    *(float2*)(un + p) = make_float2(aAc, aBc);   // p even -> aligned
}

// One full Tsit5 step for a 28x28 tile with halo-6 redundant compute;
// active region shrinks by one ring per stage. Global-OOB cells are
// weight-isolated (W=0 edges), so prologue loads are clamp-indexed and
// unconditionally vectorized; no pong/guard zeroing needed either.
__global__ void __launch_bounds__(NTHR, 2)
step_kernel(int par, const float* __restrict__ z, float* __restrict__ fin) {
    __shared__ __align__(16) float sA_raw[SBUF];   // act(u) ping (+guard space)
    __shared__ __align__(16) float sB_raw[SBUF];   // act(u) pong (+guard space)
    float* const sA_buf = sA_raw + REG;
    float* const sB_buf = sB_raw + REG;

    const float* __restrict__ y_in  = par ? g_yB : g_yA;
    float*       __restrict__ y_out = par ? g_yA : g_yB;

    const int tid = threadIdx.x;
    const int r0 = (int)blockIdx.y * TS - H;
    const int c0 = (int)blockIdx.x * TS - H;

    // fill ping body with act(y) (zero-padded OOB), division-free walker.
    // NTHR = 19*REG + 8 => per iteration: flr += 19, flc += 8 (with wrap).
    {
        int flr = tid / REG;
        int flc = tid - flr * REG;
        int pp = tid;
        while (pp < REG2) {
            int r = r0 + flr, c = c0 + flc;
            bool in = ((unsigned)r < NR) & ((unsigned)c < NC);
            sA_buf[pp] = in ? act(y_in[r * NC + c]) : 0.0f;
            pp += NTHR;
            flc += 8;
            if (flc >= REG) { flc -= REG; flr += 1; }
            flr += 19;
        }
    }

    // per-thread pair assignment: row lr in [1,39), cols (lc, lc+1), lc EVEN.
    // Threads >= NPAIR alias pair 0 (benign: same-value smem writes, inn=0).
    int qt = (tid < NPAIR) ? tid : 0;
    int pr = qt / NPR;
    int pc = qt - pr * NPR;
    int lr = 1 + pr;
    int lc = 2 * pc;            // 0,2,...,38
    int p  = lr * REG + lc;

    // last active stage: S <= smax  (region [S, REG-S) rows; cols intersect)
    int smax = min(min(lr, REG - 1 - lr), min(lc + 1, REG - 1 - lc));

    int rA = r0 + lr, cA = c0 + lc;
    // clamped, even global index (garbage at borders is weight-isolated)
    int rcl = min(max(rA, 0), NR - 1);
    int ccl = min(max(cA, 0), NC - 2);          // keep even for float2 alignment
    int gA = rcl * NC + ccl;

    // inner-output masks (true index == clamped index whenever these hold)
    bool innA = (lr >= H) & (lr < H + TS) & (lc     >= H) & (lc     < H + TS)
              & (rA < NR) & (cA < NC);
    bool innB = (lr >= H) & (lr < H + TS) & (lc + 1 >= H) & (lc + 1 < H + TS)
              & (rA < NR) & (cA + 1 < NC);

    float2 zv = *(const float2*)(z + gA);
    float2 yv = *(const float2*)(y_in + gA);
    float zA = zv.x, zB = zv.y, yA = yv.x, yB = yv.y;

    float wA[8], wB[8];
#pragma unroll
    for (int o = 0; o < 8; o++) {
        float2 wv = *(const float2*)(g_W + (size_t)o * NN + gA);
        wA[o] = wv.x; wB[o] = wv.y;
    }

    float uAc = yA, uBc = yB;
    float aAc = act(yA), aBc = act(yB);
    float kA[5], kB[5];

    __syncthreads();

    do_stage<1>(sA_buf, sB_buf, smax, p, wA, wB, kA, kB, uAc, uBc, aAc, aBc,
                yA, yB, zA, zB, innA, innB, gA, y_out, fin);
    __syncthreads();
    do_stage<2>(sB_buf, sA_buf, smax, p, wA, wB, kA, kB, uAc, uBc, aAc, aBc,
                yA, yB, zA, zB, innA, innB, gA, y_out, fin);
    __syncthreads();
    do_stage<3>(sA_buf, sB_buf, smax, p, wA, wB, kA, kB, uAc, uBc, aAc, aBc,
                yA, yB, zA, zB, innA, innB, gA, y_out, fin);
    __syncthreads();
    do_stage<4>(sB_buf, sA_buf, smax, p, wA, wB, kA, kB, uAc, uBc, aAc, aBc,
                yA, yB, zA, zB, innA, innB, gA, y_out, fin);
    __syncthreads();
    do_stage<5>(sA_buf, sB_buf, smax, p, wA, wB, kA, kB, uAc, uBc, aAc, aBc,
                yA, yB, zA, zB, innA, innB, gA, y_out, fin);
    __syncthreads();
    do_stage<6>(sB_buf, sA_buf, smax, p, wA, wB, kA, kB, uAc, uBc, aAc, aBc,
                yA, yB, zA, zB, innA, innB, gA, y_out, fin);
}

extern "C" void kernel_launch(void* const* d_in, const int* in_sizes, int n_in,
                              void* d_out, int out_size) {
    const float* x   = (const float*)d_in[0];
    const float* z   = (const float*)d_in[1];
    const float* k   = (const float*)d_in[2];
    const int*   src = (const int*)d_in[3];
    const int*   dst = (const int*)d_in[4];
    int ne = in_sizes[2];

    init_kernel<<<(NN + 511) / 512, 512>>>(x);
    scatter_W<<<(ne + 511) / 512, 512>>>(k, src, dst, ne);

    dim3 grid(NTILE, NTILE);   // 37 x 37 tiles of 28x28
    for (int s = 0; s < 32; s++) {
        float* fin = (s == 31) ? (float*)d_out : nullptr;  // last step: fused clip -> d_out
        step_kernel<<<grid, NTHR>>>(s & 1, z, fin);
    }
}